// round 5
// baseline (speedup 1.0000x reference)
#include <cuda_runtime.h>
#include <cstdint>

// ---------------------------------------------------------------------------
// Problem constants
// ---------------------------------------------------------------------------
#define T_STEPS 2048
#define BATCH   64
#define INSZ    512
#define HID     256
#define G4      1024      // 4*HID
#define OUTSZ   128
#define MROWS   (T_STEPS * BATCH)   // 131072

// Scratch (device globals: allocation-free per harness rules)
__device__ float g_Xp[(size_t)MROWS * G4];   // input projection + biases
__device__ float g_hs[(size_t)MROWS * HID];  // hidden states

// ---------------------------------------------------------------------------
// Packed fp32x2 FMA (SASS FFMA2) — used in the recurrence.
// ---------------------------------------------------------------------------
__device__ __forceinline__ void ffma2(float2& d, const float2& a, const float2& b)
{
    asm("fma.rn.f32x2 %0, %1, %2, %0;"
        : "+l"(reinterpret_cast<unsigned long long&>(d))
        : "l"(reinterpret_cast<const unsigned long long&>(a)),
          "l"(reinterpret_cast<const unsigned long long&>(b)));
}

// ---------------------------------------------------------------------------
// 3xTF32 tensor-core GEMM (NT) — unchanged from round 4.
// ---------------------------------------------------------------------------
__device__ __forceinline__ float2 split_tf32(float x)
{
    uint32_t h;
    asm("cvt.rna.tf32.f32 %0, %1;" : "=r"(h) : "f"(x));
    float hf = __uint_as_float(h);
    float lo = x - hf;
    uint32_t l;
    asm("cvt.rna.tf32.f32 %0, %1;" : "=r"(l) : "f"(lo));
    return make_float2(hf, __uint_as_float(l));
}

#define MMA_TF32(d, a0, a1, a2, a3, b0, b1)                                   \
    asm("mma.sync.aligned.m16n8k8.row.col.f32.tf32.tf32.f32 "                  \
        "{%0,%1,%2,%3},{%4,%5,%6,%7},{%8,%9},{%0,%1,%2,%3};"                   \
        : "+f"((d)[0]), "+f"((d)[1]), "+f"((d)[2]), "+f"((d)[3])               \
        : "r"(a0), "r"(a1), "r"(a2), "r"(a3), "r"(b0), "r"(b1))

#define SPAD 18   // float2 row stride (16 K + 2 pad)

__global__ void __launch_bounds__(256)
tgemm128(const float* __restrict__ A, const float* __restrict__ Bm,
         const float* __restrict__ bias1, const float* __restrict__ bias2,
         float* __restrict__ C, int K, int N)
{
    __shared__ float2 As[128][SPAD];   // (hi, lo) pairs
    __shared__ float2 Bs[128][SPAD];

    const int tid  = threadIdx.x;
    const int lane = tid & 31;
    const int warp = tid >> 5;
    const int wm = warp & 1;
    const int wn = warp >> 1;
    const int g  = lane >> 2;
    const int t  = lane & 3;

    const size_t m0 = (size_t)blockIdx.x * 128;
    const int    n0 = blockIdx.y * 128;

    const int lrow = tid >> 1;
    const int lc   = (tid & 1) * 8;
    const float* Ag = A  + (m0 + lrow) * (size_t)K + lc;
    const float* Bg = Bm + (size_t)(n0 + lrow) * K + lc;

    float acc[4][4][4];
#pragma unroll
    for (int i = 0; i < 4; ++i)
#pragma unroll
        for (int j = 0; j < 4; ++j)
#pragma unroll
            for (int q = 0; q < 4; ++q) acc[i][j][q] = 0.f;

    for (int k0 = 0; k0 < K; k0 += 16) {
        float4 av0 = *(const float4*)(Ag + k0);
        float4 av1 = *(const float4*)(Ag + k0 + 4);
        float4 bv0 = *(const float4*)(Bg + k0);
        float4 bv1 = *(const float4*)(Bg + k0 + 4);
        __syncthreads();
        As[lrow][lc + 0] = split_tf32(av0.x);
        As[lrow][lc + 1] = split_tf32(av0.y);
        As[lrow][lc + 2] = split_tf32(av0.z);
        As[lrow][lc + 3] = split_tf32(av0.w);
        As[lrow][lc + 4] = split_tf32(av1.x);
        As[lrow][lc + 5] = split_tf32(av1.y);
        As[lrow][lc + 6] = split_tf32(av1.z);
        As[lrow][lc + 7] = split_tf32(av1.w);
        Bs[lrow][lc + 0] = split_tf32(bv0.x);
        Bs[lrow][lc + 1] = split_tf32(bv0.y);
        Bs[lrow][lc + 2] = split_tf32(bv0.z);
        Bs[lrow][lc + 3] = split_tf32(bv0.w);
        Bs[lrow][lc + 4] = split_tf32(bv1.x);
        Bs[lrow][lc + 5] = split_tf32(bv1.y);
        Bs[lrow][lc + 6] = split_tf32(bv1.z);
        Bs[lrow][lc + 7] = split_tf32(bv1.w);
        __syncthreads();

#pragma unroll
        for (int ks = 0; ks < 2; ++ks) {
            const int kb = ks * 8;
            uint32_t ah[4][4], al[4][4], bh[4][2], bl[4][2];
#pragma unroll
            for (int i = 0; i < 4; ++i) {
                int row = wm * 64 + i * 16 + g;
                float2 v00 = As[row][kb + t];
                float2 v10 = As[row + 8][kb + t];
                float2 v01 = As[row][kb + t + 4];
                float2 v11 = As[row + 8][kb + t + 4];
                ah[i][0] = __float_as_uint(v00.x);
                ah[i][1] = __float_as_uint(v10.x);
                ah[i][2] = __float_as_uint(v01.x);
                ah[i][3] = __float_as_uint(v11.x);
                al[i][0] = __float_as_uint(v00.y);
                al[i][1] = __float_as_uint(v10.y);
                al[i][2] = __float_as_uint(v01.y);
                al[i][3] = __float_as_uint(v11.y);
            }
#pragma unroll
            for (int j = 0; j < 4; ++j) {
                int n = wn * 32 + j * 8 + g;
                float2 w0 = Bs[n][kb + t];
                float2 w1 = Bs[n][kb + t + 4];
                bh[j][0] = __float_as_uint(w0.x);
                bh[j][1] = __float_as_uint(w1.x);
                bl[j][0] = __float_as_uint(w0.y);
                bl[j][1] = __float_as_uint(w1.y);
            }
#pragma unroll
            for (int i = 0; i < 4; ++i)
#pragma unroll
                for (int j = 0; j < 4; ++j) {
                    MMA_TF32(acc[i][j], ah[i][0], ah[i][1], ah[i][2], ah[i][3],
                             bh[j][0], bh[j][1]);
                    MMA_TF32(acc[i][j], ah[i][0], ah[i][1], ah[i][2], ah[i][3],
                             bl[j][0], bl[j][1]);
                    MMA_TF32(acc[i][j], al[i][0], al[i][1], al[i][2], al[i][3],
                             bh[j][0], bh[j][1]);
                }
        }
    }

#pragma unroll
    for (int j = 0; j < 4; ++j) {
        int col = n0 + wn * 32 + j * 8 + 2 * t;
        float b0 = bias1[col], b1 = bias1[col + 1];
        if (bias2) { b0 += bias2[col]; b1 += bias2[col + 1]; }
#pragma unroll
        for (int i = 0; i < 4; ++i) {
            size_t row = m0 + wm * 64 + i * 16 + g;
            *(float2*)(C + row * N + col) =
                make_float2(acc[i][j][0] + b0, acc[i][j][1] + b1);
            *(float2*)(C + (row + 8) * N + col) =
                make_float2(acc[i][j][2] + b0, acc[i][j][3] + b1);
        }
    }
}

// ---------------------------------------------------------------------------
// mbarrier helpers
// ---------------------------------------------------------------------------
__device__ __forceinline__ void mbar_init(uint32_t addr, uint32_t count)
{
    asm volatile("mbarrier.init.shared.b64 [%0], %1;" :: "r"(addr), "r"(count)
                 : "memory");
}
__device__ __forceinline__ void mbar_expect_tx(uint32_t addr, uint32_t bytes)
{
    asm volatile("mbarrier.arrive.expect_tx.shared.b64 _, [%0], %1;"
                 :: "r"(addr), "r"(bytes) : "memory");
}
__device__ __forceinline__ void mbar_wait(uint32_t addr, uint32_t parity)
{
    asm volatile(
        "{\n\t"
        ".reg .pred P;\n\t"
        "LW%=:\n\t"
        "mbarrier.try_wait.parity.acquire.cta.shared::cta.b64 P, [%0], %1, 0x989680;\n\t"
        "@P bra LD%=;\n\t"
        "bra LW%=;\n\t"
        "LD%=:\n\t"
        "}"
        :: "r"(addr), "r"(parity) : "memory");
}

// ---------------------------------------------------------------------------
// LSTM recurrence v2: persistent clustered kernel, register weights,
// mbarrier + cp.async.bulk h-exchange (NO cluster barrier in the loop).
//
// 16 clusters x 8 CTAs x 256 threads. Cluster cl owns batches [cl*4, cl*4+4).
// CTA rank r owns h outputs j = r*32 + jj (all 4 gates).
// Thread (warp w, lane): gates rr=0..3 of output jj=lane, K chunk
// [w*32,(w+1)*32), weights in 64 f32x2 registers (K-pair packed FFMA2).
//
// h ring: hsm[slot=3][rank=8][batch=4][32]. Slot s holds the h input for
// step t with t%3==s. Fill tracked by mbar[s] via expect_tx(4096) +
// 8x cp.async.bulk (512B from each rank). WAR safety: waiting fill(t)
// implies every peer consumed h(t-1), i.e. all our older bulks delivered.
// ---------------------------------------------------------------------------
__global__ void __launch_bounds__(256, 1)
lstm_rec_kernel(const float* __restrict__ Whh,
                const float* __restrict__ Xp,
                float* __restrict__ hs)
{
    __shared__ float  hsm[3 * 1024];          // [slot][rank][batch][32]
    __shared__ float4 part[8][4][32];         // [warp][batch][jj] = 4 gates
    __shared__ float  hstage[128];            // [batch*32 + jj]
    __shared__ __align__(8) unsigned long long mbar[3];

    const int tid  = threadIdx.x;
    const int lane = tid & 31;
    const int w    = tid >> 5;

    unsigned r;
    asm("mov.u32 %0, %%cluster_ctarank;" : "=r"(r));
    const int cl = blockIdx.x >> 3;

    const uint32_t hsm_s = (uint32_t)__cvta_generic_to_shared(hsm);
    const uint32_t hst_s = (uint32_t)__cvta_generic_to_shared(hstage);
    const uint32_t mb_s  = (uint32_t)__cvta_generic_to_shared(mbar);

    // Weights: gate rr, output jj=lane, k-chunk w*32..w*32+31.
    float2 wreg[4][16];
#pragma unroll
    for (int rr = 0; rr < 4; ++rr) {
        int grow = rr * 256 + (int)r * 32 + lane;
        const float2* wp = (const float2*)(Whh + (size_t)grow * 256 + w * 32);
#pragma unroll
        for (int k2 = 0; k2 < 16; ++k2) wreg[rr][k2] = wp[k2];
    }
    for (int i = tid; i < 3 * 1024; i += 256) hsm[i] = 0.f;  // slot0 = h0 = 0
    if (tid == 0) {
        mbar_init(mb_s + 0, 1);
        mbar_init(mb_s + 8, 1);
        mbar_init(mb_s + 16, 1);
    }
    __syncthreads();
    // All CTAs' mbarriers + slot0 ready before any peer pushes.
    asm volatile("barrier.cluster.arrive.aligned;" ::: "memory");
    asm volatile("barrier.cluster.wait.aligned;"   ::: "memory");

    const int bb = tid >> 5;   // reducer batch (tid<128)
    const int jj = tid & 31;
    float c = 0.f;             // cell state (tid<128)
    int par = 0;               // per-slot phase parity bits
    int rs = 0;                // t % 3

    for (int t = 0; t < T_STEPS; ++t) {
        const int ws = (rs == 2) ? 0 : rs + 1;

        // Announce expected bytes for the slot we are about to fill.
        if (tid == 0 && t < T_STEPS - 1)
            mbar_expect_tx(mb_s + ws * 8, 4096u);

        // Wait for this step's h input (slot rs). t=0: prefilled zeros.
        if (t > 0) {
            mbar_wait(mb_s + rs * 8, (par >> rs) & 1);
        }

        // Early-issue Xp loads (covered by the dot loop).
        float xq0 = 0.f, xq1 = 0.f, xq2 = 0.f, xq3 = 0.f;
        if (tid < 128) {
            const float* xp = Xp + ((size_t)t * 64 + cl * 4 + bb) * 1024
                                 + (int)r * 32 + jj;
            xq0 = xp[0]; xq1 = xp[256]; xq2 = xp[512]; xq3 = xp[768];
        }

        // Dot phase: warp w consumes rank-block w of slot rs.
        float2 acc[4][4];
#pragma unroll
        for (int rr = 0; rr < 4; ++rr)
#pragma unroll
            for (int b = 0; b < 4; ++b) acc[rr][b] = make_float2(0.f, 0.f);

        const float* hb = hsm + rs * 1024 + w * 128;   // [batch][32]
#pragma unroll
        for (int k2 = 0; k2 < 16; ++k2) {
            float2 h0 = *(const float2*)(hb + 2 * k2);
            float2 h1 = *(const float2*)(hb + 32 + 2 * k2);
            float2 h2 = *(const float2*)(hb + 64 + 2 * k2);
            float2 h3 = *(const float2*)(hb + 96 + 2 * k2);
#pragma unroll
            for (int rr = 0; rr < 4; ++rr) {
                ffma2(acc[rr][0], wreg[rr][k2], h0);
                ffma2(acc[rr][1], wreg[rr][k2], h1);
                ffma2(acc[rr][2], wreg[rr][k2], h2);
                ffma2(acc[rr][3], wreg[rr][k2], h3);
            }
        }
        // Gate-major partials: one float4 (i,f,g,o) per (batch, jj).
#pragma unroll
        for (int b = 0; b < 4; ++b) {
            part[w][b][lane] = make_float4(acc[0][b].x + acc[0][b].y,
                                           acc[1][b].x + acc[1][b].y,
                                           acc[2][b].x + acc[2][b].y,
                                           acc[3][b].x + acc[3][b].y);
        }
        __syncthreads();

        if (tid < 128) {
            float s0 = xq0, s1 = xq1, s2 = xq2, s3 = xq3;
#pragma unroll
            for (int w8 = 0; w8 < 8; ++w8) {
                float4 p = part[w8][bb][jj];
                s0 += p.x; s1 += p.y; s2 += p.z; s3 += p.w;
            }
            float ig = 1.f / (1.f + __expf(-s0));
            float fg = 1.f / (1.f + __expf(-s1));
            float e2 = __expf(2.f * s2);
            float gg = (e2 - 1.f) / (e2 + 1.f);
            float og = 1.f / (1.f + __expf(-s3));
            c = fg * c + ig * gg;
            float ec = __expf(2.f * c);
            float h = og * ((ec - 1.f) / (ec + 1.f));
            hstage[tid] = h;                       // tid == bb*32 + jj

            asm volatile("bar.sync 3, 128;" ::: "memory");

            // Elected thread pushes 512B (this rank's h) to all 8 CTAs.
            if (tid == 0 && t < T_STEPS - 1) {
                asm volatile("fence.proxy.async.shared::cta;" ::: "memory");
                const uint32_t dOff = hsm_s + (uint32_t)ws * 4096u + r * 512u;
                const uint32_t mOff = mb_s + (uint32_t)ws * 8u;
#pragma unroll
                for (int dst = 0; dst < 8; ++dst) {
                    uint32_t rd, rm;
                    asm volatile("mapa.shared::cluster.u32 %0, %1, %2;"
                                 : "=r"(rd) : "r"(dOff), "r"(dst));
                    asm volatile("mapa.shared::cluster.u32 %0, %1, %2;"
                                 : "=r"(rm) : "r"(mOff), "r"(dst));
                    asm volatile(
                        "cp.async.bulk.shared::cluster.shared::cta"
                        ".mbarrier::complete_tx::bytes [%0], [%1], %2, [%3];"
                        :: "r"(rd), "r"(hst_s), "r"(512u), "r"(rm)
                        : "memory");
                }
            }
            // Global h store (off the critical path).
            hs[((size_t)t * 64 + cl * 4 + bb) * 256 + (int)r * 32 + jj] = h;
        }

        if (t > 0) par ^= (1 << rs);   // parity consumed this step
        rs = (rs == 2) ? 0 : rs + 1;
    }

    asm volatile("barrier.cluster.arrive.aligned;" ::: "memory");
    asm volatile("barrier.cluster.wait.aligned;"   ::: "memory");
}

// ---------------------------------------------------------------------------
// Launch
// ---------------------------------------------------------------------------
extern "C" void kernel_launch(void* const* d_in, const int* in_sizes, int n_in,
                              void* d_out, int out_size)
{
    const float* inputs = (const float*)d_in[0];
    const float* W_ih   = (const float*)d_in[1];
    const float* W_hh   = (const float*)d_in[2];
    const float* b_ih   = (const float*)d_in[3];
    const float* b_hh   = (const float*)d_in[4];
    const float* W_fc   = (const float*)d_in[5];
    const float* b_fc   = (const float*)d_in[6];
    float* out = (float*)d_out;

    float *Xp, *hsbuf;
    cudaGetSymbolAddress((void**)&Xp, g_Xp);
    cudaGetSymbolAddress((void**)&hsbuf, g_hs);

    // 1) Xp = inputs @ W_ih^T + (b_ih + b_hh)   [131072 x 1024], 3xTF32
    {
        dim3 grid(MROWS / 128, G4 / 128);
        tgemm128<<<grid, 256>>>(inputs, W_ih, b_ih, b_hh, Xp, INSZ, G4);
    }

    // 2) LSTM recurrence (clustered persistent kernel) -> hs [131072 x 256]
    {
        cudaLaunchConfig_t cfg = {};
        cfg.gridDim = dim3(128, 1, 1);
        cfg.blockDim = dim3(256, 1, 1);
        cfg.dynamicSmemBytes = 0;
        cfg.stream = 0;
        cudaLaunchAttribute attr[1];
        attr[0].id = cudaLaunchAttributeClusterDimension;
        attr[0].val.clusterDim.x = 8;
        attr[0].val.clusterDim.y = 1;
        attr[0].val.clusterDim.z = 1;
        cfg.attrs = attr;
        cfg.numAttrs = 1;
        cudaLaunchKernelEx(&cfg, lstm_rec_kernel, W_hh, (const float*)Xp, hsbuf);
    }

    // 3) out = hs @ W_fc^T + b_fc   [131072 x 128], 3xTF32
    {
        dim3 grid(MROWS / 128, OUTSZ / 128);
        tgemm128<<<grid, 256>>>(hsbuf, W_fc, b_fc, (const float*)nullptr, out,
                                HID, OUTSZ);
    }
}

// round 6
// speedup vs baseline: 1.2865x; 1.2865x over previous
#include <cuda_runtime.h>
#include <cstdint>

// ---------------------------------------------------------------------------
// Problem constants
// ---------------------------------------------------------------------------
#define T_STEPS 2048
#define BATCH   64
#define INSZ    512
#define HID     256
#define G4      1024      // 4*HID
#define OUTSZ   128
#define MROWS   (T_STEPS * BATCH)   // 131072

// Scratch (device globals: allocation-free per harness rules)
__device__ float g_Xp[(size_t)MROWS * G4];   // input projection + biases
__device__ float g_hs[(size_t)MROWS * HID];  // hidden states

// ---------------------------------------------------------------------------
// Packed fp32x2 FMA (SASS FFMA2) — used in the recurrence.
// ---------------------------------------------------------------------------
__device__ __forceinline__ void ffma2(float2& d, const float2& a, const float2& b)
{
    asm("fma.rn.f32x2 %0, %1, %2, %0;"
        : "+l"(reinterpret_cast<unsigned long long&>(d))
        : "l"(reinterpret_cast<const unsigned long long&>(a)),
          "l"(reinterpret_cast<const unsigned long long&>(b)));
}

// ---------------------------------------------------------------------------
// 3xTF32 tensor-core GEMM (NT) — unchanged from round 4.
// ---------------------------------------------------------------------------
__device__ __forceinline__ float2 split_tf32(float x)
{
    uint32_t h;
    asm("cvt.rna.tf32.f32 %0, %1;" : "=r"(h) : "f"(x));
    float hf = __uint_as_float(h);
    float lo = x - hf;
    uint32_t l;
    asm("cvt.rna.tf32.f32 %0, %1;" : "=r"(l) : "f"(lo));
    return make_float2(hf, __uint_as_float(l));
}

#define MMA_TF32(d, a0, a1, a2, a3, b0, b1)                                   \
    asm("mma.sync.aligned.m16n8k8.row.col.f32.tf32.tf32.f32 "                  \
        "{%0,%1,%2,%3},{%4,%5,%6,%7},{%8,%9},{%0,%1,%2,%3};"                   \
        : "+f"((d)[0]), "+f"((d)[1]), "+f"((d)[2]), "+f"((d)[3])               \
        : "r"(a0), "r"(a1), "r"(a2), "r"(a3), "r"(b0), "r"(b1))

#define SPAD 18   // float2 row stride (16 K + 2 pad)

__global__ void __launch_bounds__(256)
tgemm128(const float* __restrict__ A, const float* __restrict__ Bm,
         const float* __restrict__ bias1, const float* __restrict__ bias2,
         float* __restrict__ C, int K, int N)
{
    __shared__ float2 As[128][SPAD];   // (hi, lo) pairs
    __shared__ float2 Bs[128][SPAD];

    const int tid  = threadIdx.x;
    const int lane = tid & 31;
    const int warp = tid >> 5;
    const int wm = warp & 1;
    const int wn = warp >> 1;
    const int g  = lane >> 2;
    const int t  = lane & 3;

    const size_t m0 = (size_t)blockIdx.x * 128;
    const int    n0 = blockIdx.y * 128;

    const int lrow = tid >> 1;
    const int lc   = (tid & 1) * 8;
    const float* Ag = A  + (m0 + lrow) * (size_t)K + lc;
    const float* Bg = Bm + (size_t)(n0 + lrow) * K + lc;

    float acc[4][4][4];
#pragma unroll
    for (int i = 0; i < 4; ++i)
#pragma unroll
        for (int j = 0; j < 4; ++j)
#pragma unroll
            for (int q = 0; q < 4; ++q) acc[i][j][q] = 0.f;

    for (int k0 = 0; k0 < K; k0 += 16) {
        float4 av0 = *(const float4*)(Ag + k0);
        float4 av1 = *(const float4*)(Ag + k0 + 4);
        float4 bv0 = *(const float4*)(Bg + k0);
        float4 bv1 = *(const float4*)(Bg + k0 + 4);
        __syncthreads();
        As[lrow][lc + 0] = split_tf32(av0.x);
        As[lrow][lc + 1] = split_tf32(av0.y);
        As[lrow][lc + 2] = split_tf32(av0.z);
        As[lrow][lc + 3] = split_tf32(av0.w);
        As[lrow][lc + 4] = split_tf32(av1.x);
        As[lrow][lc + 5] = split_tf32(av1.y);
        As[lrow][lc + 6] = split_tf32(av1.z);
        As[lrow][lc + 7] = split_tf32(av1.w);
        Bs[lrow][lc + 0] = split_tf32(bv0.x);
        Bs[lrow][lc + 1] = split_tf32(bv0.y);
        Bs[lrow][lc + 2] = split_tf32(bv0.z);
        Bs[lrow][lc + 3] = split_tf32(bv0.w);
        Bs[lrow][lc + 4] = split_tf32(bv1.x);
        Bs[lrow][lc + 5] = split_tf32(bv1.y);
        Bs[lrow][lc + 6] = split_tf32(bv1.z);
        Bs[lrow][lc + 7] = split_tf32(bv1.w);
        __syncthreads();

#pragma unroll
        for (int ks = 0; ks < 2; ++ks) {
            const int kb = ks * 8;
            uint32_t ah[4][4], al[4][4], bh[4][2], bl[4][2];
#pragma unroll
            for (int i = 0; i < 4; ++i) {
                int row = wm * 64 + i * 16 + g;
                float2 v00 = As[row][kb + t];
                float2 v10 = As[row + 8][kb + t];
                float2 v01 = As[row][kb + t + 4];
                float2 v11 = As[row + 8][kb + t + 4];
                ah[i][0] = __float_as_uint(v00.x);
                ah[i][1] = __float_as_uint(v10.x);
                ah[i][2] = __float_as_uint(v01.x);
                ah[i][3] = __float_as_uint(v11.x);
                al[i][0] = __float_as_uint(v00.y);
                al[i][1] = __float_as_uint(v10.y);
                al[i][2] = __float_as_uint(v01.y);
                al[i][3] = __float_as_uint(v11.y);
            }
#pragma unroll
            for (int j = 0; j < 4; ++j) {
                int n = wn * 32 + j * 8 + g;
                float2 w0 = Bs[n][kb + t];
                float2 w1 = Bs[n][kb + t + 4];
                bh[j][0] = __float_as_uint(w0.x);
                bh[j][1] = __float_as_uint(w1.x);
                bl[j][0] = __float_as_uint(w0.y);
                bl[j][1] = __float_as_uint(w1.y);
            }
#pragma unroll
            for (int i = 0; i < 4; ++i)
#pragma unroll
                for (int j = 0; j < 4; ++j) {
                    MMA_TF32(acc[i][j], ah[i][0], ah[i][1], ah[i][2], ah[i][3],
                             bh[j][0], bh[j][1]);
                    MMA_TF32(acc[i][j], ah[i][0], ah[i][1], ah[i][2], ah[i][3],
                             bl[j][0], bl[j][1]);
                    MMA_TF32(acc[i][j], al[i][0], al[i][1], al[i][2], al[i][3],
                             bh[j][0], bh[j][1]);
                }
        }
    }

#pragma unroll
    for (int j = 0; j < 4; ++j) {
        int col = n0 + wn * 32 + j * 8 + 2 * t;
        float b0 = bias1[col], b1 = bias1[col + 1];
        if (bias2) { b0 += bias2[col]; b1 += bias2[col + 1]; }
#pragma unroll
        for (int i = 0; i < 4; ++i) {
            size_t row = m0 + wm * 64 + i * 16 + g;
            *(float2*)(C + row * N + col) =
                make_float2(acc[i][j][0] + b0, acc[i][j][1] + b1);
            *(float2*)(C + (row + 8) * N + col) =
                make_float2(acc[i][j][2] + b0, acc[i][j][3] + b1);
        }
    }
}

// ---------------------------------------------------------------------------
// mbarrier helpers
// ---------------------------------------------------------------------------
__device__ __forceinline__ void mbar_init(uint32_t addr, uint32_t count)
{
    asm volatile("mbarrier.init.shared.b64 [%0], %1;" :: "r"(addr), "r"(count)
                 : "memory");
}
__device__ __forceinline__ void mbar_expect_tx(uint32_t addr, uint32_t bytes)
{
    asm volatile("mbarrier.arrive.expect_tx.shared.b64 _, [%0], %1;"
                 :: "r"(addr), "r"(bytes) : "memory");
}
__device__ __forceinline__ void mbar_wait(uint32_t addr, uint32_t parity)
{
    asm volatile(
        "{\n\t"
        ".reg .pred P;\n\t"
        "LW%=:\n\t"
        "mbarrier.try_wait.parity.acquire.cta.shared::cta.b64 P, [%0], %1;\n\t"
        "@P bra LD%=;\n\t"
        "bra LW%=;\n\t"
        "LD%=:\n\t"
        "}"
        :: "r"(addr), "r"(parity) : "memory");
}

// ---------------------------------------------------------------------------
// LSTM recurrence v3: per-(slot,rank) mbarriers + st.async direct scatter.
//
// 16 clusters x 8 CTAs x 256 threads. Cluster cl owns batches [cl*4, cl*4+4).
// CTA rank r owns h outputs j = r*32 + jj (all 4 gates).
// Warp w consumes ONLY rank w's 512B h-block each step -> waits only
// mbar[slot][w], so cross-CTA skew overlaps with the dot phase instead of
// serializing in front of it.
//
// h ring: hsm[slot=3][rank=8][batch=4][32]. Producer rank r's 128 reducer
// threads each scatter their single h value to all 8 peers with
// st.async (completes mbar[slot][r] on each peer, 512B per phase).
// Re-arm: expect_tx(512) on consumed slot's 8 barriers right after
// __syncthreads (2 steps before next arrivals; provably race-free).
// ---------------------------------------------------------------------------
__global__ void __launch_bounds__(256, 1)
lstm_rec_kernel(const float* __restrict__ Whh,
                const float* __restrict__ Xp,
                float* __restrict__ hs)
{
    __shared__ float  hsm[3 * 1024];          // [slot][rank][batch][32]
    __shared__ float4 part[8][4][32];         // [warp][batch][jj] = 4 gates
    __shared__ __align__(8) unsigned long long mbar[24];  // [slot][rank]

    const int tid  = threadIdx.x;
    const int lane = tid & 31;
    const int w    = tid >> 5;

    unsigned r;
    asm("mov.u32 %0, %%cluster_ctarank;" : "=r"(r));
    const int cl = blockIdx.x >> 3;

    const uint32_t hsm_s = (uint32_t)__cvta_generic_to_shared(hsm);
    const uint32_t mb_s  = (uint32_t)__cvta_generic_to_shared(mbar);

    // Per-peer base addresses (cluster windows), computed once.
    uint32_t pd[8], pm[8];
#pragma unroll
    for (int dst = 0; dst < 8; ++dst) {
        asm("mapa.shared::cluster.u32 %0, %1, %2;"
            : "=r"(pd[dst]) : "r"(hsm_s), "r"(dst));
        asm("mapa.shared::cluster.u32 %0, %1, %2;"
            : "=r"(pm[dst]) : "r"(mb_s), "r"(dst));
    }

    // Weights: gate rr, output jj=lane, k-chunk w*32..w*32+31 (64 f32x2 regs).
    float2 wreg[4][16];
#pragma unroll
    for (int rr = 0; rr < 4; ++rr) {
        int grow = rr * 256 + (int)r * 32 + lane;
        const float2* wp = (const float2*)(Whh + (size_t)grow * 256 + w * 32);
#pragma unroll
        for (int k2 = 0; k2 < 16; ++k2) wreg[rr][k2] = wp[k2];
    }
    for (int i = tid; i < 3 * 1024; i += 256) hsm[i] = 0.f;  // slot0 = h0 = 0
    if (tid < 24) mbar_init(mb_s + tid * 8, 1);
    __syncthreads();
    if (tid < 24) mbar_expect_tx(mb_s + tid * 8, 512u);      // arm phase 0, all
    // All CTAs' barriers + slot0 zeros visible before any peer pushes.
    asm volatile("barrier.cluster.arrive.aligned;" ::: "memory");
    asm volatile("barrier.cluster.wait.aligned;"   ::: "memory");

    const int bb = tid >> 5;   // reducer batch (tid<128)
    const int jj = tid & 31;
    float c = 0.f;             // cell state (tid<128)
    int par = 0;               // per-slot phase parity bits
    int rs = 0;                // t % 3

    // Prefetch Xp for t=0.
    const float* xp_base = Xp + ((size_t)cl * 4 + bb) * 1024 + (int)r * 32 + jj;
    float xc0 = 0.f, xc1 = 0.f, xc2 = 0.f, xc3 = 0.f;
    if (tid < 128) {
        xc0 = xp_base[0]; xc1 = xp_base[256];
        xc2 = xp_base[512]; xc3 = xp_base[768];
    }

    for (int t = 0; t < T_STEPS; ++t) {
        const int ws = (rs == 2) ? 0 : rs + 1;

        // Wait for this step's h block (rank w only). t=0: prefilled zeros.
        if (t > 0)
            mbar_wait(mb_s + (rs * 8 + w) * 8, (par >> rs) & 1);

        // Prefetch Xp for t+1 (consumed next iteration; ~full step of slack).
        float xn0 = 0.f, xn1 = 0.f, xn2 = 0.f, xn3 = 0.f;
        if (tid < 128 && t + 1 < T_STEPS) {
            const float* xp = xp_base + (size_t)(t + 1) * 64 * 1024;
            xn0 = xp[0]; xn1 = xp[256]; xn2 = xp[512]; xn3 = xp[768];
        }

        // Dot phase: warp w consumes rank-block w of slot rs.
        float2 acc[4][4];
#pragma unroll
        for (int rr = 0; rr < 4; ++rr)
#pragma unroll
            for (int b = 0; b < 4; ++b) acc[rr][b] = make_float2(0.f, 0.f);

        const float* hb = hsm + rs * 1024 + w * 128;   // [batch][32]
#pragma unroll
        for (int k2 = 0; k2 < 16; ++k2) {
            float2 h0 = *(const float2*)(hb + 2 * k2);
            float2 h1 = *(const float2*)(hb + 32 + 2 * k2);
            float2 h2 = *(const float2*)(hb + 64 + 2 * k2);
            float2 h3 = *(const float2*)(hb + 96 + 2 * k2);
#pragma unroll
            for (int rr = 0; rr < 4; ++rr) {
                ffma2(acc[rr][0], wreg[rr][k2], h0);
                ffma2(acc[rr][1], wreg[rr][k2], h1);
                ffma2(acc[rr][2], wreg[rr][k2], h2);
                ffma2(acc[rr][3], wreg[rr][k2], h3);
            }
        }
        // Gate-major partials: one float4 (i,f,g,o) per (batch, jj).
#pragma unroll
        for (int b = 0; b < 4; ++b) {
            part[w][b][lane] = make_float4(acc[0][b].x + acc[0][b].y,
                                           acc[1][b].x + acc[1][b].y,
                                           acc[2][b].x + acc[2][b].y,
                                           acc[3][b].x + acc[3][b].y);
        }
        __syncthreads();

        // Re-arm consumed slot's barriers for its next phase (off-path;
        // next arrivals are 2 steps away).
        if (t > 0 && tid < 8)
            mbar_expect_tx(mb_s + (rs * 8 + tid) * 8, 512u);

        if (tid < 128) {
            float s0 = xc0, s1 = xc1, s2 = xc2, s3 = xc3;
#pragma unroll
            for (int w8 = 0; w8 < 8; ++w8) {
                float4 p = part[w8][bb][jj];
                s0 += p.x; s1 += p.y; s2 += p.z; s3 += p.w;
            }
            float ig = __fdividef(1.f, 1.f + __expf(-s0));
            float fg = __fdividef(1.f, 1.f + __expf(-s1));
            float e2 = __expf(2.f * s2);
            float gg = __fdividef(e2 - 1.f, e2 + 1.f);
            float og = __fdividef(1.f, 1.f + __expf(-s3));
            c = fg * c + ig * gg;
            float ec = __expf(2.f * c);
            float h = og * __fdividef(ec - 1.f, ec + 1.f);

            // Direct scatter: this thread's h -> all 8 peers' slot ws,
            // completing mbar[ws][r] on each (512B per barrier per phase).
            if (t < T_STEPS - 1) {
                uint32_t hv = __float_as_uint(h);
                uint32_t doff = (uint32_t)ws * 4096u + r * 512u
                              + (uint32_t)tid * 4u;
                uint32_t moff = ((uint32_t)ws * 8u + r) * 8u;
#pragma unroll
                for (int dst = 0; dst < 8; ++dst) {
                    asm volatile(
                        "st.async.shared::cluster.mbarrier::complete_tx::bytes"
                        ".u32 [%0], %1, [%2];"
                        :: "r"(pd[dst] + doff), "r"(hv), "r"(pm[dst] + moff)
                        : "memory");
                }
            }
            // Global h store (off the critical path).
            hs[((size_t)t * 64 + cl * 4 + bb) * 256 + (int)r * 32 + jj] = h;
        }

        // Rotate prefetched Xp.
        xc0 = xn0; xc1 = xn1; xc2 = xn2; xc3 = xn3;

        if (t > 0) par ^= (1 << rs);   // phase consumed this step
        rs = (rs == 2) ? 0 : rs + 1;
    }

    asm volatile("barrier.cluster.arrive.aligned;" ::: "memory");
    asm volatile("barrier.cluster.wait.aligned;"   ::: "memory");
}

// ---------------------------------------------------------------------------
// Launch
// ---------------------------------------------------------------------------
extern "C" void kernel_launch(void* const* d_in, const int* in_sizes, int n_in,
                              void* d_out, int out_size)
{
    const float* inputs = (const float*)d_in[0];
    const float* W_ih   = (const float*)d_in[1];
    const float* W_hh   = (const float*)d_in[2];
    const float* b_ih   = (const float*)d_in[3];
    const float* b_hh   = (const float*)d_in[4];
    const float* W_fc   = (const float*)d_in[5];
    const float* b_fc   = (const float*)d_in[6];
    float* out = (float*)d_out;

    float *Xp, *hsbuf;
    cudaGetSymbolAddress((void**)&Xp, g_Xp);
    cudaGetSymbolAddress((void**)&hsbuf, g_hs);

    // 1) Xp = inputs @ W_ih^T + (b_ih + b_hh)   [131072 x 1024], 3xTF32
    {
        dim3 grid(MROWS / 128, G4 / 128);
        tgemm128<<<grid, 256>>>(inputs, W_ih, b_ih, b_hh, Xp, INSZ, G4);
    }

    // 2) LSTM recurrence (clustered persistent kernel) -> hs [131072 x 256]
    {
        cudaLaunchConfig_t cfg = {};
        cfg.gridDim = dim3(128, 1, 1);
        cfg.blockDim = dim3(256, 1, 1);
        cfg.dynamicSmemBytes = 0;
        cfg.stream = 0;
        cudaLaunchAttribute attr[1];
        attr[0].id = cudaLaunchAttributeClusterDimension;
        attr[0].val.clusterDim.x = 8;
        attr[0].val.clusterDim.y = 1;
        attr[0].val.clusterDim.z = 1;
        cfg.attrs = attr;
        cfg.numAttrs = 1;
        cudaLaunchKernelEx(&cfg, lstm_rec_kernel, W_hh, (const float*)Xp, hsbuf);
    }

    // 3) out = hs @ W_fc^T + b_fc   [131072 x 128], 3xTF32
    {
        dim3 grid(MROWS / 128, OUTSZ / 128);
        tgemm128<<<grid, 256>>>(hsbuf, W_fc, b_fc, (const float*)nullptr, out,
                                HID, OUTSZ);
    }
}